// round 2
// baseline (speedup 1.0000x reference)
#include <cuda_runtime.h>

// SpectralConv2d via truncated-mode DFTs (no FFT library).
// x[16,64,256,256] -> rfft2 -> keep (ky in {0..19} U {236..255}) x (kx in 0..19)
// -> complex channel mix (w1 top / w2 bottom) -> irfft2 (pocketfft c2r semantics:
// imaginary part of the kx=0 bin is ignored).

#define BB 16
#define CC 64
#define HH 256
#define WW 256
#define M1 20
#define M2 20
#define QQ 40   // 2*M1 retained ky rows, stored in "q" order: q<20 -> ky=236+q (bottom), q>=20 -> ky=q-20 (top)

// Scratch (device globals; allocation-free)
__device__ float2 g_Y1[BB*CC*HH*M2];   // after W-DFT   [b,c,h,k2]   41.9 MB
__device__ float2 g_Zq[BB*CC*QQ*M2];   // after H-DFT   [b,c,q,k2]    6.6 MB
__device__ float2 g_Zo[BB*CC*QQ*M2];   // after mixing  [b,o,q,k2]    6.6 MB
__device__ float2 g_G [BB*CC*HH*M2];   // after inv-H   [b,o,h,k2]   41.9 MB

// ---------------------------------------------------------------------------
// Stage A: Y1[row,k] = sum_w x[row,w] * e^{-2*pi*i*k*w/256},  k=0..19
// one thread per (row,k); phase recurrence (rotate by e^{-2*pi*i*k/256}).
// ---------------------------------------------------------------------------
__global__ void kA(const float* __restrict__ x) {
    int idx = blockIdx.x * blockDim.x + threadIdx.x;
    if (idx >= BB*CC*HH*M2) return;
    int k   = idx % M2;
    int row = idx / M2;
    const float* xr = x + (size_t)row * WW;

    float sa, ca;
    sincospif((float)k * (1.0f/128.0f), &sa, &ca);   // angle 2*pi*k/256 = pi*(k/128)
    float cr = 1.0f, ci = 0.0f;                       // e^{-i*theta*w}, w=0
    float ar = 0.0f, ai = 0.0f;

    #pragma unroll 8
    for (int w = 0; w < WW; ++w) {
        float xv = __ldg(&xr[w]);
        ar = fmaf(xv, cr, ar);
        ai = fmaf(xv, ci, ai);
        // rotate by e^{-i*theta}: (cr,ci) <- (cr*ca + ci*sa, ci*ca - cr*sa)
        float t = fmaf(cr, ca,  ci * sa);
        ci      = fmaf(ci, ca, -cr * sa);
        cr = t;
    }
    g_Y1[idx] = make_float2(ar, ai);
}

// ---------------------------------------------------------------------------
// Stage B: Zq[b,c,q,k2] = sum_h Y1[b,c,h,k2] * e^{-2*pi*i*ky(q)*h/256}
// ---------------------------------------------------------------------------
__global__ void kB() {
    int idx = blockIdx.x * blockDim.x + threadIdx.x;
    if (idx >= BB*CC*QQ*M2) return;
    int k2 = idx % M2;
    int q  = (idx / M2) % QQ;
    int bc = idx / (M2 * QQ);
    int ky = (q < M1) ? (HH - M1 + q) : (q - M1);   // 236+q (bottom) or q-20 (top)

    float sa, ca;
    sincospif((float)ky * (1.0f/128.0f), &sa, &ca);
    float cr = 1.0f, ci = 0.0f;                      // e^{-i*phi*h}
    float ar = 0.0f, ai = 0.0f;

    const float2* yrow = g_Y1 + (size_t)bc * HH * M2 + k2;
    #pragma unroll 8
    for (int h = 0; h < HH; ++h) {
        float2 Y = yrow[(size_t)h * M2];
        ar += Y.x * cr - Y.y * ci;
        ai += Y.x * ci + Y.y * cr;
        float t = fmaf(cr, ca,  ci * sa);
        ci      = fmaf(ci, ca, -cr * sa);
        cr = t;
    }
    g_Zq[idx] = make_float2(ar, ai);
}

// ---------------------------------------------------------------------------
// Stage C: Zo[b,o,q,k2] = sum_i Zq[b,i,q,k2] * Wsel[i,o,m,k2]
//   q >= M1 (top rows, ky=q-20):     w1, m = q-20
//   q <  M1 (bottom rows, ky=236+q): w2, m = q
// ---------------------------------------------------------------------------
__global__ void kC(const float* __restrict__ w1r, const float* __restrict__ w1i,
                   const float* __restrict__ w2r, const float* __restrict__ w2i) {
    int idx = blockIdx.x * blockDim.x + threadIdx.x;
    if (idx >= BB*CC*QQ*M2) return;
    int k2 = idx % M2;
    int q  = (idx / M2) % QQ;
    int o  = (idx / (M2 * QQ)) % CC;
    int b  = idx / (M2 * QQ * CC);

    const float *wr, *wi;
    int m;
    if (q < M1) { wr = w2r; wi = w2i; m = q; }
    else        { wr = w1r; wi = w1i; m = q - M1; }

    float ar = 0.0f, ai = 0.0f;
    #pragma unroll 4
    for (int i = 0; i < CC; ++i) {
        float2 Z = g_Zq[(((size_t)(b*CC + i) * QQ) + q) * M2 + k2];
        size_t widx = (((size_t)(i*CC + o) * M1) + m) * M2 + k2;
        float wrv = __ldg(&wr[widx]);
        float wiv = __ldg(&wi[widx]);
        ar += Z.x * wrv - Z.y * wiv;
        ai += Z.x * wiv + Z.y * wrv;
    }
    g_Zo[idx] = make_float2(ar, ai);
}

// ---------------------------------------------------------------------------
// Stage D1: G[b,o,h,k2] = sum_q Zo[b,o,q,k2] * e^{+2*pi*i*ky(q)*h/256}
// q order corresponds to frequency f = q-20 in [-20,19]; uniform phase step
// e^{+2*pi*i*h/256}, starting at e^{-2*pi*i*20*h/256}.
// ---------------------------------------------------------------------------
__global__ void kD1() {
    int idx = blockIdx.x * blockDim.x + threadIdx.x;
    if (idx >= BB*CC*HH*M2) return;
    int k2 = idx % M2;
    int h  = (idx / M2) % HH;
    int bo = idx / (M2 * HH);

    float sa, ca;
    sincospif((float)h * (1.0f/128.0f), &sa, &ca);   // step e^{+2*pi*i*h/256}
    int ph = (20 * h) & 255;                          // 20h mod 256
    float s0, c0;
    sincospif((float)ph * (1.0f/128.0f), &s0, &c0);
    float cr = c0, ci = -s0;                          // e^{-2*pi*i*20*h/256}

    float ar = 0.0f, ai = 0.0f;
    const float2* zrow = g_Zo + (size_t)bo * QQ * M2 + k2;
    #pragma unroll
    for (int q = 0; q < QQ; ++q) {
        float2 Z = zrow[(size_t)q * M2];
        ar += Z.x * cr - Z.y * ci;
        ai += Z.x * ci + Z.y * cr;
        // rotate positive: (cr,ci) <- (cr*ca - ci*sa, cr*sa + ci*ca)
        float t = fmaf(cr, ca, -ci * sa);
        ci      = fmaf(cr, sa,  ci * ca);
        cr = t;
    }
    g_G[idx] = make_float2(ar, ai);
}

// ---------------------------------------------------------------------------
// Stage D2: out[row,w] = (1/65536) * [ Re G[row,0]
//                         + 2 * sum_{k=1..19} Re( G[row,k] * e^{+2*pi*i*k*w/256} ) ]
// (c2r semantics: imag of kx=0 bin dropped; Nyquist bin is zero.)
// One block per row (b,o,h), 256 threads = w.
// ---------------------------------------------------------------------------
__global__ void kD2(float* __restrict__ out) {
    int row = blockIdx.x;          // b*CC*HH + ...
    int w   = threadIdx.x;         // 0..255
    __shared__ float2 sG[M2];
    if (threadIdx.x < M2) sG[threadIdx.x] = g_G[(size_t)row * M2 + threadIdx.x];
    __syncthreads();

    float sa, ca;
    sincospif((float)w * (1.0f/128.0f), &sa, &ca);   // e^{+2*pi*i*w/256}
    float cr = ca, ci = sa;                           // phase for k=1
    float acc = sG[0].x;
    #pragma unroll
    for (int k = 1; k < M2; ++k) {
        acc += 2.0f * (sG[k].x * cr - sG[k].y * ci);
        float t = fmaf(cr, ca, -ci * sa);
        ci      = fmaf(cr, sa,  ci * ca);
        cr = t;
    }
    out[(size_t)row * WW + w] = acc * (1.0f / 65536.0f);
}

extern "C" void kernel_launch(void* const* d_in, const int* in_sizes, int n_in,
                              void* d_out, int out_size) {
    const float* x   = (const float*)d_in[0];
    const float* w1r = (const float*)d_in[1];
    const float* w1i = (const float*)d_in[2];
    const float* w2r = (const float*)d_in[3];
    const float* w2i = (const float*)d_in[4];
    float* out = (float*)d_out;

    const int NA = BB*CC*HH*M2;   // 5,242,880
    const int NB = BB*CC*QQ*M2;   //   819,200

    kA <<<(NA + 255) / 256, 256>>>(x);
    kB <<<(NB + 255) / 256, 256>>>();
    kC <<<(NB + 255) / 256, 256>>>(w1r, w1i, w2r, w2i);
    kD1<<<(NA + 255) / 256, 256>>>();
    kD2<<<BB*CC*HH, 256>>>(out);
}

// round 3
// speedup vs baseline: 1.6829x; 1.6829x over previous
#include <cuda_runtime.h>

// SpectralConv2d via truncated-mode DFTs, fp32 SIMT, twiddle tables + folding.
// x[16,64,256,256] -> rfft2 -> keep (ky in {0..19} U {236..255}) x (kx 0..19)
// -> complex channel mix (w1 top / w2 bottom) -> irfft2.

#define BB 16
#define CC 64
#define HH 256
#define WW 256
#define M1 20
#define M2 20
#define QQ 40   // q<20 -> ky=236+q (w2, m=q); q>=20 -> ky=q-20 (w1, m=q-20); freq f = q-20

// Scratch (device globals; allocation-free)
__device__ float2 g_Y1[BB*CC*HH*M2];   // after W-DFT   [b,c,h,k2]   41.9 MB
__device__ float2 g_Zq[BB*CC*QQ*M2];   // after H-DFT   [b,c,q,k2]    6.6 MB
__device__ float2 g_Zo[BB*CC*QQ*M2];   // after mixing  [b,o,q,k2]    6.6 MB

// ---------------------------------------------------------------------------
// Stage A: Y1[row,k] = sum_w x[row,w] e^{-2pi i k w/256}, k=0..19.
// Folded: u=x[w]+x[256-w], v=x[w]-x[256-w] (w=1..127), plus x[0], x[128]:
//   Re = x0 + (-1)^k x128 + sum u*cos ;  Im = -sum v*sin
// Block: 128 rows, 256 threads; thread -> (2 rows, 5 k). Twiddle via smem table.
// ---------------------------------------------------------------------------
#define RA 128
#define WCH 32
__global__ void __launch_bounds__(256) kA(const float* __restrict__ x) {
    __shared__ float2 tw[256];
    __shared__ float2 sf[RA][WCH + 1];   // (u,v) chunk; [..][0] of chunk0 = (x0,x128)
    int tid = threadIdx.x;
    {
        float s, c;
        sincospif((float)tid * (1.0f / 128.0f), &s, &c);
        tw[tid] = make_float2(c, s);
    }
    int row0 = blockIdx.x * RA;
    int rp = tid >> 2;             // 0..63 -> rows 2rp, 2rp+1
    int k0 = (tid & 3) * 5;        // 5 k per thread

    float ar[2][5], ai[2][5];
    #pragma unroll
    for (int u = 0; u < 2; ++u)
        #pragma unroll
        for (int j = 0; j < 5; ++j) { ar[u][j] = 0.0f; ai[u][j] = 0.0f; }

    float2 e0 = make_float2(0.f, 0.f), e1 = make_float2(0.f, 0.f);  // (x0, x128) per row

    for (int wc = 0; wc < 128; wc += WCH) {
        __syncthreads();
        for (int t = tid; t < RA * WCH; t += 256) {
            int r = t >> 5, wl = t & 31;
            int w = wc + wl;
            const float* xr = x + (size_t)(row0 + r) * WW;
            float a = xr[w];
            if (w == 0) {
                sf[r][wl] = make_float2(a, xr[128]);
            } else {
                float b = xr[256 - w];
                sf[r][wl] = make_float2(a + b, a - b);
            }
        }
        __syncthreads();

        int wl0 = 0;
        if (wc == 0) {
            e0 = sf[2 * rp][0];
            e1 = sf[2 * rp + 1][0];
            wl0 = 1;
        }
        int id[5];
        #pragma unroll
        for (int j = 0; j < 5; ++j) id[j] = ((k0 + j) * (wc + wl0)) & 255;

        for (int wl = wl0; wl < WCH; ++wl) {
            float2 uv0 = sf[2 * rp][wl];
            float2 uv1 = sf[2 * rp + 1][wl];
            #pragma unroll
            for (int j = 0; j < 5; ++j) {
                float2 cs = tw[id[j]];
                ar[0][j] = fmaf(uv0.x, cs.x, ar[0][j]);
                ai[0][j] = fmaf(uv0.y, cs.y, ai[0][j]);
                ar[1][j] = fmaf(uv1.x, cs.x, ar[1][j]);
                ai[1][j] = fmaf(uv1.y, cs.y, ai[1][j]);
                id[j] = (id[j] + k0 + j) & 255;
            }
        }
    }

    #pragma unroll
    for (int u = 0; u < 2; ++u) {
        float2 e = (u == 0) ? e0 : e1;
        float2* yo = g_Y1 + (size_t)(row0 + 2 * rp + u) * M2;
        #pragma unroll
        for (int j = 0; j < 5; ++j) {
            int k = k0 + j;
            float re = ar[u][j] + e.x + ((k & 1) ? -e.y : e.y);
            yo[k] = make_float2(re, -ai[u][j]);
        }
    }
}

// ---------------------------------------------------------------------------
// Stage B: Zq[bc,q,k2] = sum_h Y1[bc,h,k2] e^{-2pi i f h/256}, f=q-20.
// Block per bc; Y tile (40KB) in smem; thread -> (q, 4 k2). Table twiddles.
// ---------------------------------------------------------------------------
__global__ void __launch_bounds__(256) kB() {
    __shared__ float2 tw[256];
    __shared__ float2 sY[HH][M2];  // 40KB
    int tid = threadIdx.x;
    {
        float s, c;
        sincospif((float)tid * (1.0f / 128.0f), &s, &c);
        tw[tid] = make_float2(c, s);
    }
    int bc = blockIdx.x;
    const float4* s4 = (const float4*)(g_Y1 + (size_t)bc * HH * M2);
    float4* d4 = (float4*)&sY[0][0];
    for (int t = tid; t < HH * M2 / 2; t += 256) d4[t] = s4[t];
    __syncthreads();

    if (tid < 200) {
        int q = tid / 5;
        int k0 = (tid % 5) * 4;
        int f = q - M1;
        float ar[4] = {0, 0, 0, 0}, ai[4] = {0, 0, 0, 0};
        int idx = 0;
        #pragma unroll 4
        for (int h = 0; h < HH; ++h) {
            float2 cs = tw[idx & 255];
            #pragma unroll
            for (int j = 0; j < 4; ++j) {
                float2 Y = sY[h][k0 + j];
                // e^{-i th}: ar += Yx c + Yy s ; ai += Yy c - Yx s
                ar[j] = fmaf(Y.x, cs.x, fmaf(Y.y, cs.y, ar[j]));
                ai[j] = fmaf(Y.y, cs.x, fmaf(-Y.x, cs.y, ai[j]));
            }
            idx += f;
        }
        float2* zo = g_Zq + (size_t)bc * QQ * M2 + q * M2 + k0;
        #pragma unroll
        for (int j = 0; j < 4; ++j) zo[j] = make_float2(ar[j], ai[j]);
    }
}

// ---------------------------------------------------------------------------
// Stage C: Zo[b,o,q,k2] = sum_i Zq[b,i,q,k2] * Wsel[i,o,m,k2]  (complex)
// Block per (q,k2); Z[16][64] in smem (W read once per block, serves 16 b).
// ---------------------------------------------------------------------------
__global__ void __launch_bounds__(256) kC(const float* __restrict__ w1r, const float* __restrict__ w1i,
                                          const float* __restrict__ w2r, const float* __restrict__ w2i) {
    __shared__ float2 sZ[BB][CC];  // 8KB
    int tid = threadIdx.x;
    int q = blockIdx.x / M2, k2 = blockIdx.x % M2;

    for (int t = tid; t < BB * CC; t += 256)
        sZ[t >> 6][t & 63] = g_Zq[(size_t)t * (QQ * M2) + q * M2 + k2];

    const float *wr, *wi;
    int m;
    if (q < M1) { wr = w2r; wi = w2i; m = q; }
    else        { wr = w1r; wi = w1i; m = q - M1; }
    __syncthreads();

    int o = tid & 63;
    int bq = tid >> 6;   // b = bq + 4j
    float ar[4] = {0, 0, 0, 0}, ai[4] = {0, 0, 0, 0};
    size_t wbase = (size_t)o * (M1 * M2) + m * M2 + k2;
    #pragma unroll 4
    for (int i = 0; i < CC; ++i) {
        float wrv = __ldg(&wr[wbase + (size_t)i * (CC * M1 * M2)]);
        float wiv = __ldg(&wi[wbase + (size_t)i * (CC * M1 * M2)]);
        #pragma unroll
        for (int j = 0; j < 4; ++j) {
            float2 Z = sZ[bq + 4 * j][i];
            ar[j] = fmaf(Z.x, wrv, fmaf(-Z.y, wiv, ar[j]));
            ai[j] = fmaf(Z.x, wiv, fmaf(Z.y, wrv, ai[j]));
        }
    }
    #pragma unroll
    for (int j = 0; j < 4; ++j) {
        int b = bq + 4 * j;
        g_Zo[(((size_t)(b * CC + o)) * QQ + q) * M2 + k2] = make_float2(ar[j], ai[j]);
    }
}

// ---------------------------------------------------------------------------
// Stage D (fused D1+D2): per (bo, 32-h tile):
//   phase1: G[h,k] = sum_q Zo[bo,q,k] e^{+2pi i (q-20)h/256}  (into smem)
//   phase2: out[h,w] = (g0 + 2 sum_{k>=1} Re(G[h,k] e^{+2pi i k w/256})) / 65536
//   folded over w<->256-w: C=g0/2+sum Gx c, S=sum Gy s; out[w]=2(C-S), out[256-w]=2(C+S)
//   thread w=0 handles (w=0, w=128) via c_k=(k even), s_k=-(k odd) with Gx.
// ---------------------------------------------------------------------------
#define HT 32
__global__ void __launch_bounds__(256) kD(float* __restrict__ out) {
    __shared__ float2 tw[256];
    __shared__ float2 sZ[QQ][M2];  // 6.25KB
    __shared__ float2 sG[HT][M2];  // 5KB
    int tid = threadIdx.x;
    {
        float s, c;
        sincospif((float)tid * (1.0f / 128.0f), &s, &c);
        tw[tid] = make_float2(c, s);
    }
    int bo = blockIdx.x >> 3;
    int h0 = (blockIdx.x & 7) * HT;

    const float4* zsrc = (const float4*)(g_Zo + (size_t)bo * QQ * M2);
    float4* zdst = (float4*)&sZ[0][0];
    for (int t = tid; t < QQ * M2 / 2; t += 256) zdst[t] = zsrc[t];
    __syncthreads();

    // phase 1
    for (int u = tid; u < HT * M2; u += 256) {
        int h = u / M2, k = u - h * M2;
        int hh = h0 + h;
        float ar = 0.f, ai = 0.f;
        int idx = (-M1 * hh) & 255;
        int step = hh & 255;
        #pragma unroll 4
        for (int q = 0; q < QQ; ++q) {
            float2 cs = tw[idx];
            float2 Z = sZ[q][k];
            ar = fmaf(Z.x, cs.x, fmaf(-Z.y, cs.y, ar));
            ai = fmaf(Z.x, cs.y, fmaf(Z.y, cs.x, ai));
            idx = (idx + step) & 255;
        }
        sG[h][k] = make_float2(ar, ai);
    }
    __syncthreads();

    // phase 2
    int w = tid & 127;
    int hb = (tid >> 7) * 16;
    bool spec = (w == 0);
    float C[16], S[16];
    #pragma unroll
    for (int j = 0; j < 16; ++j) { C[j] = 0.5f * sG[hb + j][0].x; S[j] = 0.f; }

    float cr, ci, ca, sa;
    {
        float s, c;
        sincospif((float)w * (1.0f / 128.0f), &s, &c);
        cr = c; ci = s; ca = c; sa = s;   // phase for k=1; step e^{+2pi i w/256}
    }
    for (int k = 1; k < M2; ++k) {
        float cu, su;
        if (spec) { cu = (k & 1) ? 0.f : 1.f; su = (k & 1) ? -1.f : 0.f; }
        else      { cu = cr; su = ci; }
        #pragma unroll
        for (int j = 0; j < 16; ++j) {
            float2 G = sG[hb + j][k];
            float gy = spec ? G.x : G.y;
            C[j] = fmaf(G.x, cu, C[j]);
            S[j] = fmaf(gy, su, S[j]);
        }
        float t = fmaf(cr, ca, -ci * sa);
        ci = fmaf(cr, sa, ci * ca);
        cr = t;
    }
    int wm = spec ? 128 : 256 - w;
    const float sc = 2.0f / 65536.0f;
    size_t base = ((size_t)bo * HH + h0 + hb) * WW;
    #pragma unroll
    for (int j = 0; j < 16; ++j) {
        out[base + (size_t)j * WW + w]  = (C[j] - S[j]) * sc;
        out[base + (size_t)j * WW + wm] = (C[j] + S[j]) * sc;
    }
}

extern "C" void kernel_launch(void* const* d_in, const int* in_sizes, int n_in,
                              void* d_out, int out_size) {
    const float* x   = (const float*)d_in[0];
    const float* w1r = (const float*)d_in[1];
    const float* w1i = (const float*)d_in[2];
    const float* w2r = (const float*)d_in[3];
    const float* w2i = (const float*)d_in[4];
    float* out = (float*)d_out;

    kA<<<(BB * CC * HH) / RA, 256>>>(x);       // 2048 blocks
    kB<<<BB * CC, 256>>>();                     // 1024 blocks
    kC<<<QQ * M2, 256>>>(w1r, w1i, w2r, w2i);   // 800 blocks
    kD<<<BB * CC * (HH / HT), 256>>>(out);      // 8192 blocks
}

// round 4
// speedup vs baseline: 2.1667x; 1.2874x over previous
#include <cuda_runtime.h>

// SpectralConv2d via truncated-mode DFTs, fp32 SIMT, register-tiled.
// x[16,64,256,256] -> rfft2 -> keep (ky in {0..19} U {236..255}) x (kx 0..19)
// -> complex channel mix (w1 top / w2 bottom) -> irfft2.

#define BB 16
#define CC 64
#define HH 256
#define WW 256
#define M1 20
#define M2 20
#define QQ 40   // q<20 -> ky=236+q (w2, m=q); q>=20 -> ky=q-20 (w1, m=q-20); freq f = q-20

// Scratch (device globals; allocation-free)
__device__ float2 g_Y1[BB*CC*HH*M2];   // after W-DFT   [b,c,h,k2]   41.9 MB
__device__ float2 g_Zq[BB*CC*QQ*M2];   // after H-DFT   [b,c,q,k2]    6.6 MB
__device__ float2 g_Zo[BB*CC*QQ*M2];   // after mixing  [b,o,q,k2]    6.6 MB

// ---------------------------------------------------------------------------
// Stage A: Y1[row,k] = sum_w x[row,w] e^{-2pi i k w/256}, k=0..19.
// Folded real input: u=x[w]+x[256-w], v=x[w]-x[256-w] (w=1..127), + x[0],x[128].
// Block: 128 rows, 256 threads; thread -> (2 rows, 5 k). Twiddles from a
// per-chunk smem tile twa[wl][k] (no index ALU in the hot loop).
// ---------------------------------------------------------------------------
#define RA 128
#define WCH 32
__global__ void __launch_bounds__(256) kA(const float* __restrict__ x) {
    __shared__ float2 tw[256];
    __shared__ float2 sf[RA][WCH + 1];   // (u,v) chunk; [..][0] of chunk0 = (x0,x128)
    __shared__ float2 twa[WCH][M2];      // twiddles for this chunk
    int tid = threadIdx.x;
    {
        float s, c;
        sincospif((float)tid * (1.0f / 128.0f), &s, &c);
        tw[tid] = make_float2(c, s);
    }
    int row0 = blockIdx.x * RA;
    int rp = tid >> 2;             // 0..63 -> rows 2rp, 2rp+1
    int k0 = (tid & 3) * 5;        // 5 k per thread

    float ar[2][5], ai[2][5];
    #pragma unroll
    for (int u = 0; u < 2; ++u)
        #pragma unroll
        for (int j = 0; j < 5; ++j) { ar[u][j] = 0.0f; ai[u][j] = 0.0f; }

    float2 e0 = make_float2(0.f, 0.f), e1 = make_float2(0.f, 0.f);  // (x0, x128) per row

    for (int wc = 0; wc < 128; wc += WCH) {
        __syncthreads();
        for (int t = tid; t < RA * WCH; t += 256) {
            int r = t >> 5, wl = t & 31;
            int w = wc + wl;
            const float* xr = x + (size_t)(row0 + r) * WW;
            float a = xr[w];
            if (w == 0) {
                sf[r][wl] = make_float2(a, xr[128]);
            } else {
                float b = xr[256 - w];
                sf[r][wl] = make_float2(a + b, a - b);
            }
        }
        for (int t = tid; t < WCH * M2; t += 256) {
            int wl = t / M2, k = t - wl * M2;
            twa[wl][k] = tw[((wc + wl) * k) & 255];
        }
        __syncthreads();

        int wl0 = 0;
        if (wc == 0) {
            e0 = sf[2 * rp][0];
            e1 = sf[2 * rp + 1][0];
            wl0 = 1;
        }

        #pragma unroll 4
        for (int wl = wl0; wl < WCH; ++wl) {
            float2 uv0 = sf[2 * rp][wl];
            float2 uv1 = sf[2 * rp + 1][wl];
            #pragma unroll
            for (int j = 0; j < 5; ++j) {
                float2 cs = twa[wl][k0 + j];
                ar[0][j] = fmaf(uv0.x, cs.x, ar[0][j]);
                ai[0][j] = fmaf(uv0.y, cs.y, ai[0][j]);
                ar[1][j] = fmaf(uv1.x, cs.x, ar[1][j]);
                ai[1][j] = fmaf(uv1.y, cs.y, ai[1][j]);
            }
        }
    }

    #pragma unroll
    for (int u = 0; u < 2; ++u) {
        float2 e = (u == 0) ? e0 : e1;
        float2* yo = g_Y1 + (size_t)(row0 + 2 * rp + u) * M2;
        #pragma unroll
        for (int j = 0; j < 5; ++j) {
            int k = k0 + j;
            float re = ar[u][j] + e.x + ((k & 1) ? -e.y : e.y);
            yo[k] = make_float2(re, -ai[u][j]);
        }
    }
}

// ---------------------------------------------------------------------------
// Stage B: Zq[bc,q,k2] = sum_h Y1[bc,h,k2] e^{-2pi i f h/256}, f=q-20.
// Fold h <-> h+128: e^{-i f (h+128)...} = e^{-ifh...} * (-1)^f.
//   Zq = sum_{h<128} (Y[h] + (-1)^f Y[h+128]) * e^{-2pi i f h/256}
// Block per bc; Yp/Ym tiles in smem; thread -> (q, 4 k2).
// ---------------------------------------------------------------------------
__global__ void __launch_bounds__(256) kB() {
    __shared__ float2 tw[256];
    __shared__ float2 sYp[128][M2];  // 20KB
    __shared__ float2 sYm[128][M2];  // 20KB
    int tid = threadIdx.x;
    {
        float s, c;
        sincospif((float)tid * (1.0f / 128.0f), &s, &c);
        tw[tid] = make_float2(c, s);
    }
    int bc = blockIdx.x;
    const float2* ysrc = g_Y1 + (size_t)bc * HH * M2;
    for (int t = tid; t < 128 * M2; t += 256) {
        int h = t / M2, k = t - h * M2;
        float2 a = ysrc[t];
        float2 b = ysrc[t + 128 * M2];
        sYp[h][k] = make_float2(a.x + b.x, a.y + b.y);
        sYm[h][k] = make_float2(a.x - b.x, a.y - b.y);
    }
    __syncthreads();

    if (tid < 200) {
        int q = tid / 5;
        int k0 = (tid % 5) * 4;
        int f = q - M1;
        const float2 (*Ys)[M2] = (f & 1) ? sYm : sYp;
        float ar[4] = {0, 0, 0, 0}, ai[4] = {0, 0, 0, 0};
        int idx = 0, step = f & 255;
        #pragma unroll 4
        for (int h = 0; h < 128; ++h) {
            float2 cs = tw[idx];
            #pragma unroll
            for (int j = 0; j < 4; ++j) {
                float2 Y = Ys[h][k0 + j];
                ar[j] = fmaf(Y.x, cs.x, fmaf(Y.y, cs.y, ar[j]));
                ai[j] = fmaf(Y.y, cs.x, fmaf(-Y.x, cs.y, ai[j]));
            }
            idx = (idx + step) & 255;
        }
        float2* zo = g_Zq + (size_t)bc * QQ * M2 + q * M2 + k0;
        #pragma unroll
        for (int j = 0; j < 4; ++j) zo[j] = make_float2(ar[j], ai[j]);
    }
}

// ---------------------------------------------------------------------------
// Stage C: Zo[b,o,q,k2] = sum_i Zq[b,i,q,k2] * Wsel[i,o,m,k2]  (complex)
// Block per (q,k2); Z[16][64] in smem (W read once per block, serves 16 b).
// ---------------------------------------------------------------------------
__global__ void __launch_bounds__(256) kC(const float* __restrict__ w1r, const float* __restrict__ w1i,
                                          const float* __restrict__ w2r, const float* __restrict__ w2i) {
    __shared__ float2 sZ[BB][CC];  // 8KB
    int tid = threadIdx.x;
    int q = blockIdx.x / M2, k2 = blockIdx.x % M2;

    for (int t = tid; t < BB * CC; t += 256)
        sZ[t >> 6][t & 63] = g_Zq[(size_t)t * (QQ * M2) + q * M2 + k2];

    const float *wr, *wi;
    int m;
    if (q < M1) { wr = w2r; wi = w2i; m = q; }
    else        { wr = w1r; wi = w1i; m = q - M1; }
    __syncthreads();

    int o = tid & 63;
    int bq = tid >> 6;   // b = bq + 4j
    float ar[4] = {0, 0, 0, 0}, ai[4] = {0, 0, 0, 0};
    size_t wbase = (size_t)o * (M1 * M2) + m * M2 + k2;
    #pragma unroll 4
    for (int i = 0; i < CC; ++i) {
        float wrv = __ldg(&wr[wbase + (size_t)i * (CC * M1 * M2)]);
        float wiv = __ldg(&wi[wbase + (size_t)i * (CC * M1 * M2)]);
        #pragma unroll
        for (int j = 0; j < 4; ++j) {
            float2 Z = sZ[bq + 4 * j][i];
            ar[j] = fmaf(Z.x, wrv, fmaf(-Z.y, wiv, ar[j]));
            ai[j] = fmaf(Z.x, wiv, fmaf(Z.y, wrv, ai[j]));
        }
    }
    #pragma unroll
    for (int j = 0; j < 4; ++j) {
        int b = bq + 4 * j;
        g_Zo[(((size_t)(b * CC + o)) * QQ + q) * M2 + k2] = make_float2(ar[j], ai[j]);
    }
}

// ---------------------------------------------------------------------------
// Stage D (fused): block = one bo (grid 1024).
// phase1: G[h,k] = sum_q Zo[q,k] e^{+2pi i (q-20)h/256}, folded h<->h+128 via
//         even/odd-q partial sums (e^{i f 128 th} = (-1)^f, f parity = q parity).
//         Stored transposed: sGx[k][h], sGy[k-1][h] (Gy of k=0 unused by c2r).
// phase2: out[h,w] = 2/65536 * (C -/+ S) for w=wp / 256-wp, where
//         C = 0.5*Gx[0,h] + sum_{k>=1} Gx[k,h] cos(2pi k wp/256)
//         S =              sum_{k>=1} Gy[k,h] sin(2pi k wp/256)
//         Register tile 4h x 8wp; twiddles via per-wp rotation recurrence in
//         registers (ILP-8 chains). w=128 column via separate epilogue.
// ---------------------------------------------------------------------------
__global__ void __launch_bounds__(256) kD(float* __restrict__ out) {
    __shared__ float2 tw[256];          // 2KB
    __shared__ float2 sZ[QQ][M2];       // 6.25KB
    __shared__ float  sGx[M2][HH];      // 20KB
    __shared__ float  sGy[M2 - 1][HH];  // 19KB
    int tid = threadIdx.x;
    {
        float s, c;
        sincospif((float)tid * (1.0f / 128.0f), &s, &c);
        tw[tid] = make_float2(c, s);
    }
    int bo = blockIdx.x;

    const float4* zsrc = (const float4*)(g_Zo + (size_t)bo * QQ * M2);
    float4* zdst = (float4*)&sZ[0][0];
    for (int t = tid; t < QQ * M2 / 2; t += 256) zdst[t] = zsrc[t];
    __syncthreads();

    // ---- phase 1 ----
    {
        int h = tid & 127;
        int k0 = (tid >> 7) * 10;     // 0 or 10
        float ger[10], gei[10], gor[10], goi[10];
        #pragma unroll
        for (int j = 0; j < 10; ++j) { ger[j] = gei[j] = gor[j] = goi[j] = 0.f; }

        int step = (2 * h) & 255;
        // even q (f even), f = -20, -18, ..., 18
        int idx = (-20 * h) & 255;
        #pragma unroll 2
        for (int qq = 0; qq < 20; ++qq) {
            float2 cs = tw[idx];
            #pragma unroll
            for (int j = 0; j < 10; ++j) {
                float2 Z = sZ[2 * qq][k0 + j];
                ger[j] = fmaf(Z.x, cs.x, fmaf(-Z.y, cs.y, ger[j]));
                gei[j] = fmaf(Z.x, cs.y, fmaf( Z.y, cs.x, gei[j]));
            }
            idx = (idx + step) & 255;
        }
        // odd q (f odd), f = -19, -17, ..., 19
        idx = (-19 * h) & 255;
        #pragma unroll 2
        for (int qq = 0; qq < 20; ++qq) {
            float2 cs = tw[idx];
            #pragma unroll
            for (int j = 0; j < 10; ++j) {
                float2 Z = sZ[2 * qq + 1][k0 + j];
                gor[j] = fmaf(Z.x, cs.x, fmaf(-Z.y, cs.y, gor[j]));
                goi[j] = fmaf(Z.x, cs.y, fmaf( Z.y, cs.x, goi[j]));
            }
            idx = (idx + step) & 255;
        }
        #pragma unroll
        for (int j = 0; j < 10; ++j) {
            int k = k0 + j;
            sGx[k][h]       = ger[j] + gor[j];
            sGx[k][h + 128] = ger[j] - gor[j];
            if (k > 0) {
                sGy[k - 1][h]       = gei[j] + goi[j];
                sGy[k - 1][h + 128] = gei[j] - goi[j];
            }
        }
    }
    __syncthreads();

    // ---- phase 2 ----
    int hg = tid >> 4;    // 0..15
    int wg = tid & 15;    // 0..15
    float c1[8], s1[8];
    #pragma unroll
    for (int b = 0; b < 8; ++b) {
        float2 t0 = tw[wg + 16 * b];
        c1[b] = t0.x; s1[b] = t0.y;
    }
    const float sc = 2.0f / 65536.0f;

    for (int it = 0; it < 4; ++it) {
        int h0 = it * 64 + hg * 4;
        float C[4][8], S[4][8], cr[8], ci[8];
        {
            float4 gx0 = *(const float4*)&sGx[0][h0];
            float g0[4] = {gx0.x, gx0.y, gx0.z, gx0.w};
            #pragma unroll
            for (int a = 0; a < 4; ++a)
                #pragma unroll
                for (int b = 0; b < 8; ++b) { C[a][b] = 0.5f * g0[a]; S[a][b] = 0.f; }
        }
        #pragma unroll
        for (int b = 0; b < 8; ++b) { cr[b] = c1[b]; ci[b] = s1[b]; }

        #pragma unroll
        for (int k = 1; k < M2; ++k) {
            float4 gx = *(const float4*)&sGx[k][h0];
            float4 gy = *(const float4*)&sGy[k - 1][h0];
            float gxa[4] = {gx.x, gx.y, gx.z, gx.w};
            float gya[4] = {gy.x, gy.y, gy.z, gy.w};
            #pragma unroll
            for (int b = 0; b < 8; ++b) {
                #pragma unroll
                for (int a = 0; a < 4; ++a) {
                    C[a][b] = fmaf(gxa[a], cr[b], C[a][b]);
                    S[a][b] = fmaf(gya[a], ci[b], S[a][b]);
                }
                float p1 = ci[b] * s1[b];
                float p2 = ci[b] * c1[b];
                float nc = fmaf(cr[b], c1[b], -p1);
                ci[b]    = fmaf(cr[b], s1[b],  p2);
                cr[b] = nc;
            }
        }

        size_t rowbase = ((size_t)bo * HH + h0) * WW;
        #pragma unroll
        for (int a = 0; a < 4; ++a) {
            #pragma unroll
            for (int b = 0; b < 8; ++b) {
                int wp = wg + 16 * b;
                out[rowbase + (size_t)a * WW + wp] = (C[a][b] - S[a][b]) * sc;
                if (wp) out[rowbase + (size_t)a * WW + (256 - wp)] = (C[a][b] + S[a][b]) * sc;
            }
        }
    }

    // ---- w = 128 column ----
    {
        int h = tid;
        float acc = 0.5f * sGx[0][h];
        #pragma unroll
        for (int k = 1; k < M2; ++k)
            acc += (k & 1) ? -sGx[k][h] : sGx[k][h];
        out[((size_t)bo * HH + h) * WW + 128] = acc * sc;
    }
}

extern "C" void kernel_launch(void* const* d_in, const int* in_sizes, int n_in,
                              void* d_out, int out_size) {
    const float* x   = (const float*)d_in[0];
    const float* w1r = (const float*)d_in[1];
    const float* w1i = (const float*)d_in[2];
    const float* w2r = (const float*)d_in[3];
    const float* w2i = (const float*)d_in[4];
    float* out = (float*)d_out;

    kA<<<(BB * CC * HH) / RA, 256>>>(x);       // 2048 blocks
    kB<<<BB * CC, 256>>>();                     // 1024 blocks
    kC<<<QQ * M2, 256>>>(w1r, w1i, w2r, w2i);   // 800 blocks
    kD<<<BB * CC, 256>>>(out);                  // 1024 blocks
}

// round 5
// speedup vs baseline: 2.2509x; 1.0389x over previous
#include <cuda_runtime.h>

// SpectralConv2d via truncated-mode DFTs, fp32 SIMT, register-tiled.
// x[16,64,256,256] -> rfft2 -> keep (ky in {0..19} U {236..255}) x (kx 0..19)
// -> complex channel mix (w1 top / w2 bottom) -> irfft2.

#define BB 16
#define CC 64
#define HH 256
#define WW 256
#define M1 20
#define M2 20
#define QQ 40   // q<20 -> ky=236+q (w2, m=q); q>=20 -> ky=q-20 (w1, m=q-20); freq f = q-20

// Scratch (device globals; allocation-free)
__device__ float2 g_Y1[BB*CC*HH*M2];   // after W-DFT   [b,c,h,k2]   41.9 MB
__device__ float2 g_Zq[BB*CC*QQ*M2];   // after H-DFT   [b,c,q,k2]    6.6 MB
__device__ float2 g_Zo[BB*CC*QQ*M2];   // after mixing  [b,o,q,k2]    6.6 MB

// ---------------------------------------------------------------------------
// Stage A: Y1[row,k] = sum_w x[row,w] e^{-2pi i k w/256}, k=0..19.
// Folded real input: u=x[w]+x[256-w], v=x[w]-x[256-w] (w=1..127), + x[0],x[128].
// Block: 128 rows, 256 threads; thread -> (2 rows, 5 k).
// ---------------------------------------------------------------------------
#define RA 128
#define WCH 32
__global__ void __launch_bounds__(256) kA(const float* __restrict__ x) {
    __shared__ float2 tw[256];
    __shared__ float2 sf[RA][WCH + 1];   // (u,v) chunk; [..][0] of chunk0 = (x0,x128)
    __shared__ float2 twa[WCH][M2];      // twiddles for this chunk
    int tid = threadIdx.x;
    {
        float s, c;
        sincospif((float)tid * (1.0f / 128.0f), &s, &c);
        tw[tid] = make_float2(c, s);
    }
    int row0 = blockIdx.x * RA;
    int rp = tid >> 2;             // 0..63 -> rows 2rp, 2rp+1
    int k0 = (tid & 3) * 5;        // 5 k per thread

    float ar[2][5], ai[2][5];
    #pragma unroll
    for (int u = 0; u < 2; ++u)
        #pragma unroll
        for (int j = 0; j < 5; ++j) { ar[u][j] = 0.0f; ai[u][j] = 0.0f; }

    float2 e0 = make_float2(0.f, 0.f), e1 = make_float2(0.f, 0.f);  // (x0, x128) per row

    for (int wc = 0; wc < 128; wc += WCH) {
        __syncthreads();
        for (int t = tid; t < RA * WCH; t += 256) {
            int r = t >> 5, wl = t & 31;
            int w = wc + wl;
            const float* xr = x + (size_t)(row0 + r) * WW;
            float a = xr[w];
            if (w == 0) {
                sf[r][wl] = make_float2(a, xr[128]);
            } else {
                float b = xr[256 - w];
                sf[r][wl] = make_float2(a + b, a - b);
            }
        }
        for (int t = tid; t < WCH * M2; t += 256) {
            int wl = t / M2, k = t - wl * M2;
            twa[wl][k] = tw[((wc + wl) * k) & 255];
        }
        __syncthreads();

        int wl0 = 0;
        if (wc == 0) {
            e0 = sf[2 * rp][0];
            e1 = sf[2 * rp + 1][0];
            wl0 = 1;
        }

        #pragma unroll 4
        for (int wl = wl0; wl < WCH; ++wl) {
            float2 uv0 = sf[2 * rp][wl];
            float2 uv1 = sf[2 * rp + 1][wl];
            #pragma unroll
            for (int j = 0; j < 5; ++j) {
                float2 cs = twa[wl][k0 + j];
                ar[0][j] = fmaf(uv0.x, cs.x, ar[0][j]);
                ai[0][j] = fmaf(uv0.y, cs.y, ai[0][j]);
                ar[1][j] = fmaf(uv1.x, cs.x, ar[1][j]);
                ai[1][j] = fmaf(uv1.y, cs.y, ai[1][j]);
            }
        }
    }

    #pragma unroll
    for (int u = 0; u < 2; ++u) {
        float2 e = (u == 0) ? e0 : e1;
        float2* yo = g_Y1 + (size_t)(row0 + 2 * rp + u) * M2;
        #pragma unroll
        for (int j = 0; j < 5; ++j) {
            int k = k0 + j;
            float re = ar[u][j] + e.x + ((k & 1) ? -e.y : e.y);
            yo[k] = make_float2(re, -ai[u][j]);
        }
    }
}

// ---------------------------------------------------------------------------
// Stage B: Zq[bc,q,k2] = sum_h Y1[bc,h,k2] e^{-2pi i f h/256}, f=q-20.
// Fold h <-> h+128 via parity of f. Block per bc; thread -> (q, 4 k2).
// ---------------------------------------------------------------------------
__global__ void __launch_bounds__(256) kB() {
    __shared__ float2 tw[256];
    __shared__ float2 sYp[128][M2];  // 20KB
    __shared__ float2 sYm[128][M2];  // 20KB
    int tid = threadIdx.x;
    {
        float s, c;
        sincospif((float)tid * (1.0f / 128.0f), &s, &c);
        tw[tid] = make_float2(c, s);
    }
    int bc = blockIdx.x;
    const float2* ysrc = g_Y1 + (size_t)bc * HH * M2;
    for (int t = tid; t < 128 * M2; t += 256) {
        int h = t / M2, k = t - h * M2;
        float2 a = ysrc[t];
        float2 b = ysrc[t + 128 * M2];
        sYp[h][k] = make_float2(a.x + b.x, a.y + b.y);
        sYm[h][k] = make_float2(a.x - b.x, a.y - b.y);
    }
    __syncthreads();

    if (tid < 200) {
        int q = tid / 5;
        int k0 = (tid % 5) * 4;
        int f = q - M1;
        const float2 (*Ys)[M2] = (f & 1) ? sYm : sYp;
        float ar[4] = {0, 0, 0, 0}, ai[4] = {0, 0, 0, 0};
        int idx = 0, step = f & 255;
        #pragma unroll 4
        for (int h = 0; h < 128; ++h) {
            float2 cs = tw[idx];
            #pragma unroll
            for (int j = 0; j < 4; ++j) {
                float2 Y = Ys[h][k0 + j];
                ar[j] = fmaf(Y.x, cs.x, fmaf(Y.y, cs.y, ar[j]));
                ai[j] = fmaf(Y.y, cs.x, fmaf(-Y.x, cs.y, ai[j]));
            }
            idx = (idx + step) & 255;
        }
        float2* zo = g_Zq + (size_t)bc * QQ * M2 + q * M2 + k0;
        #pragma unroll
        for (int j = 0; j < 4; ++j) zo[j] = make_float2(ar[j], ai[j]);
    }
}

// ---------------------------------------------------------------------------
// Stage C: Zo[b,o,q,k2] = sum_i Zq[b,i,q,k2] * Wsel[i,o,m,k2]  (complex)
// Block per (q,k2); Z[16][64] in smem (W read once per block, serves 16 b).
// ---------------------------------------------------------------------------
__global__ void __launch_bounds__(256) kC(const float* __restrict__ w1r, const float* __restrict__ w1i,
                                          const float* __restrict__ w2r, const float* __restrict__ w2i) {
    __shared__ float2 sZ[BB][CC];  // 8KB
    int tid = threadIdx.x;
    int q = blockIdx.x / M2, k2 = blockIdx.x % M2;

    for (int t = tid; t < BB * CC; t += 256)
        sZ[t >> 6][t & 63] = g_Zq[(size_t)t * (QQ * M2) + q * M2 + k2];

    const float *wr, *wi;
    int m;
    if (q < M1) { wr = w2r; wi = w2i; m = q; }
    else        { wr = w1r; wi = w1i; m = q - M1; }
    __syncthreads();

    int o = tid & 63;
    int bq = tid >> 6;   // b = bq + 4j
    float ar[4] = {0, 0, 0, 0}, ai[4] = {0, 0, 0, 0};
    size_t wbase = (size_t)o * (M1 * M2) + m * M2 + k2;
    #pragma unroll 4
    for (int i = 0; i < CC; ++i) {
        float wrv = __ldg(&wr[wbase + (size_t)i * (CC * M1 * M2)]);
        float wiv = __ldg(&wi[wbase + (size_t)i * (CC * M1 * M2)]);
        #pragma unroll
        for (int j = 0; j < 4; ++j) {
            float2 Z = sZ[bq + 4 * j][i];
            ar[j] = fmaf(Z.x, wrv, fmaf(-Z.y, wiv, ar[j]));
            ai[j] = fmaf(Z.x, wiv, fmaf(Z.y, wrv, ai[j]));
        }
    }
    #pragma unroll
    for (int j = 0; j < 4; ++j) {
        int b = bq + 4 * j;
        g_Zo[(((size_t)(b * CC + o)) * QQ + q) * M2 + k2] = make_float2(ar[j], ai[j]);
    }
}

// ---------------------------------------------------------------------------
// Stage D (fused): block = one bo (grid 1024).
// phase1: G[h,k] = sum_q Zo[q,k] e^{+2pi i (q-20)h/256}, folded h<->h+128 via
//         even/odd-q partial sums. Stored transposed: sGx[k][h], sGy[k-1][h].
// phase2: out[h,w]: C = 0.5 Gx[0,h] + sum_k Gx[k,h] cos ; S = sum_k Gy[k,h] sin
//         out[w]=2(C-S)/65536, out[256-w]=2(C+S)/65536.
//         4h x 4w register tile; twiddles from smem tables sC/sS (no rotation
//         recurrence, no index ALU). Forward stores are STG.128.
// ---------------------------------------------------------------------------
__global__ void __launch_bounds__(256) kD(float* __restrict__ out) {
    __shared__ float2 tw[256];          // 2KB
    __shared__ float2 sZ[QQ][M2];       // 6.25KB
    __shared__ float  sGx[M2][HH];      // 20KB
    __shared__ float  sGy[M2 - 1][HH];  // 19KB
    __shared__ float  sC[M2][128];      // 10KB  cos(2pi k wp/256)
    __shared__ float  sS[M2][128];      // 10KB  sin(2pi k wp/256)
    int tid = threadIdx.x;
    {
        float s, c;
        sincospif((float)tid * (1.0f / 128.0f), &s, &c);
        tw[tid] = make_float2(c, s);
    }
    int bo = blockIdx.x;

    const float4* zsrc = (const float4*)(g_Zo + (size_t)bo * QQ * M2);
    float4* zdst = (float4*)&sZ[0][0];
    for (int t = tid; t < QQ * M2 / 2; t += 256) zdst[t] = zsrc[t];
    __syncthreads();

    // ---- twiddle tables for phase 2 ----
    for (int t = tid; t < M2 * 128; t += 256) {
        int k = t >> 7, wp = t & 127;
        float2 cs = tw[(k * wp) & 255];
        sC[k][wp] = cs.x;
        sS[k][wp] = cs.y;
    }

    // ---- phase 1 ----
    {
        int h = tid & 127;
        int k0 = (tid >> 7) * 10;     // 0 or 10
        float ger[10], gei[10], gor[10], goi[10];
        #pragma unroll
        for (int j = 0; j < 10; ++j) { ger[j] = gei[j] = gor[j] = goi[j] = 0.f; }

        int step = (2 * h) & 255;
        // even q (f even), f = -20, -18, ..., 18
        int idx = (-20 * h) & 255;
        #pragma unroll 2
        for (int qq = 0; qq < 20; ++qq) {
            float2 cs = tw[idx];
            #pragma unroll
            for (int j = 0; j < 10; ++j) {
                float2 Z = sZ[2 * qq][k0 + j];
                ger[j] = fmaf(Z.x, cs.x, fmaf(-Z.y, cs.y, ger[j]));
                gei[j] = fmaf(Z.x, cs.y, fmaf( Z.y, cs.x, gei[j]));
            }
            idx = (idx + step) & 255;
        }
        // odd q (f odd), f = -19, -17, ..., 19
        idx = (-19 * h) & 255;
        #pragma unroll 2
        for (int qq = 0; qq < 20; ++qq) {
            float2 cs = tw[idx];
            #pragma unroll
            for (int j = 0; j < 10; ++j) {
                float2 Z = sZ[2 * qq + 1][k0 + j];
                gor[j] = fmaf(Z.x, cs.x, fmaf(-Z.y, cs.y, gor[j]));
                goi[j] = fmaf(Z.x, cs.y, fmaf( Z.y, cs.x, goi[j]));
            }
            idx = (idx + step) & 255;
        }
        #pragma unroll
        for (int j = 0; j < 10; ++j) {
            int k = k0 + j;
            sGx[k][h]       = ger[j] + gor[j];
            sGx[k][h + 128] = ger[j] - gor[j];
            if (k > 0) {
                sGy[k - 1][h]       = gei[j] + goi[j];
                sGy[k - 1][h + 128] = gei[j] - goi[j];
            }
        }
    }
    __syncthreads();

    // ---- phase 2: 4h x 4w tiles, twiddles from smem tables ----
    int wg = tid & 31;        // wp0 = 4*wg
    int hgb = tid >> 5;       // 0..7
    int wp0 = wg * 4;
    const float sc = 2.0f / 65536.0f;

    #pragma unroll 1
    for (int it = 0; it < 8; ++it) {
        int h0 = it * 32 + hgb * 4;
        float C[4][4], S[4][4];
        {
            float4 g0 = *(const float4*)&sGx[0][h0];
            float g0a[4] = {g0.x, g0.y, g0.z, g0.w};
            #pragma unroll
            for (int a = 0; a < 4; ++a)
                #pragma unroll
                for (int b = 0; b < 4; ++b) { C[a][b] = 0.5f * g0a[a]; S[a][b] = 0.f; }
        }
        #pragma unroll
        for (int k = 1; k < M2; ++k) {
            float4 gx = *(const float4*)&sGx[k][h0];
            float4 gy = *(const float4*)&sGy[k - 1][h0];
            float4 cv = *(const float4*)&sC[k][wp0];
            float4 sv = *(const float4*)&sS[k][wp0];
            float gxa[4] = {gx.x, gx.y, gx.z, gx.w};
            float gya[4] = {gy.x, gy.y, gy.z, gy.w};
            float cva[4] = {cv.x, cv.y, cv.z, cv.w};
            float sva[4] = {sv.x, sv.y, sv.z, sv.w};
            #pragma unroll
            for (int a = 0; a < 4; ++a)
                #pragma unroll
                for (int b = 0; b < 4; ++b) {
                    C[a][b] = fmaf(gxa[a], cva[b], C[a][b]);
                    S[a][b] = fmaf(gya[a], sva[b], S[a][b]);
                }
        }

        size_t rowbase = ((size_t)bo * HH + h0) * WW;
        #pragma unroll
        for (int a = 0; a < 4; ++a) {
            float4 fo;
            fo.x = (C[a][0] - S[a][0]) * sc;
            fo.y = (C[a][1] - S[a][1]) * sc;
            fo.z = (C[a][2] - S[a][2]) * sc;
            fo.w = (C[a][3] - S[a][3]) * sc;
            *(float4*)&out[rowbase + (size_t)a * WW + wp0] = fo;
            #pragma unroll
            for (int b = 0; b < 4; ++b) {
                int wp = wp0 + b;
                if (wp) out[rowbase + (size_t)a * WW + (256 - wp)] = (C[a][b] + S[a][b]) * sc;
            }
        }
    }

    // ---- w = 128 column ----
    {
        int h = tid;
        float acc = 0.5f * sGx[0][h];
        #pragma unroll
        for (int k = 1; k < M2; ++k)
            acc += (k & 1) ? -sGx[k][h] : sGx[k][h];
        out[((size_t)bo * HH + h) * WW + 128] = acc * sc;
    }
}

extern "C" void kernel_launch(void* const* d_in, const int* in_sizes, int n_in,
                              void* d_out, int out_size) {
    const float* x   = (const float*)d_in[0];
    const float* w1r = (const float*)d_in[1];
    const float* w1i = (const float*)d_in[2];
    const float* w2r = (const float*)d_in[3];
    const float* w2i = (const float*)d_in[4];
    float* out = (float*)d_out;

    kA<<<(BB * CC * HH) / RA, 256>>>(x);       // 2048 blocks
    kB<<<BB * CC, 256>>>();                     // 1024 blocks
    kC<<<QQ * M2, 256>>>(w1r, w1i, w2r, w2i);   // 800 blocks
    kD<<<BB * CC, 256>>>(out);                  // 1024 blocks
}